// round 12
// baseline (speedup 1.0000x reference)
#include <cuda_runtime.h>
#include <cuda_fp16.h>
#include <math.h>

// ---------------- problem constants ----------------
#define BATCH 32
#define HH 56
#define WW_ 56
#define CC 384
#define NHEAD 12
#define WS 7
#define SS 3
#define NTOK 49              // WS*WS
#define HID 1536             // 4*C
#define NWIN 64              // (H/WS)*(W/WS)
#define HD 32                // C/NH
#define BNW 2048             // B*NWIN
#define MROWS 100352         // BNW*NTOK  (divisible by 256)

// ---------------- scratch (device globals; no allocs) ----------------
__device__ __align__(16) __half g_hwin[(size_t)MROWS * CC];
__device__ __align__(16) __half g_qkv [(size_t)MROWS * 3 * CC];
__device__ __align__(16) __half g_attn[(size_t)MROWS * CC];
__device__ __align__(16) __half g_h2  [(size_t)MROWS * CC];
__device__ __align__(16) __half g_hid [(size_t)MROWS * HID];
__device__ __align__(16) __half g_wqkv [CC * 3 * CC];
__device__ __align__(16) __half g_wproj[CC * CC];
__device__ __align__(16) __half g_w1   [CC * HID];
__device__ __align__(16) __half g_w2   [HID * CC];

// window-row -> (b*3136 + h*56 + w) index in the ORIGINAL image.
__device__ __forceinline__ int win_row_to_src(int r) {
    int b   = r / (NWIN * NTOK);
    int rem = r - b * (NWIN * NTOK);
    int wi  = rem / NTOK;
    int t   = rem - wi * NTOK;
    int wh = wi >> 3, ww = wi & 7;
    int th = t / WS,  tw = t - th * WS;
    int h = wh * WS + th + SS; if (h >= HH)  h -= HH;
    int w = ww * WS + tw + SS; if (w >= WW_) w -= WW_;
    return b * (HH * WW_) + h * WW_ + w;
}

// ---------------- fp32 -> fp16 weight conversion ----------------
__global__ void f2h_kernel(const float* __restrict__ s, __half* __restrict__ d, int n) {
    int i = (blockIdx.x * blockDim.x + threadIdx.x) * 4;
    if (i < n) {
        float4 v = *(const float4*)(s + i);
        __half2* p = (__half2*)(d + i);
        p[0] = __floats2half2_rn(v.x, v.y);
        p[1] = __floats2half2_rn(v.z, v.w);
    }
}

// ---------------- LayerNorm (fp32 in, fp16 out; optional window gather) ------
template<bool GATHER>
__global__ void __launch_bounds__(128) ln_kernel(
    const float* __restrict__ xin, const float* __restrict__ gamma,
    const float* __restrict__ beta, __half* __restrict__ out)
{
    int row = blockIdx.x;
    int src = GATHER ? win_row_to_src(row) : row;
    const float* xr = xin + (size_t)src * CC;
    int t = threadIdx.x;
    float v0 = xr[t], v1 = xr[t + 128], v2 = xr[t + 256];
    float s  = v0 + v1 + v2;
    float ss = v0 * v0 + v1 * v1 + v2 * v2;
    __shared__ float sh[16];
    #pragma unroll
    for (int o = 16; o; o >>= 1) {
        s  += __shfl_down_sync(0xffffffffu, s,  o);
        ss += __shfl_down_sync(0xffffffffu, ss, o);
    }
    int warp = t >> 5, lane = t & 31;
    if (lane == 0) { sh[warp] = s; sh[warp + 4] = ss; }
    __syncthreads();
    if (t == 0) {
        float S  = sh[0] + sh[1] + sh[2] + sh[3];
        float Q  = sh[4] + sh[5] + sh[6] + sh[7];
        float m  = S * (1.0f / CC);
        float var = Q * (1.0f / CC) - m * m;
        sh[8] = m; sh[9] = rsqrtf(var + 1e-5f);
    }
    __syncthreads();
    float m = sh[8], rinv = sh[9];
    __half* orow = out + (size_t)row * CC;
    orow[t]       = __float2half((v0 - m) * rinv * gamma[t]       + beta[t]);
    orow[t + 128] = __float2half((v1 - m) * rinv * gamma[t + 128] + beta[t + 128]);
    orow[t + 256] = __float2half((v2 - m) * rinv * gamma[t + 256] + beta[t + 256]);
}

// ---------------- fp16 tensor-core GEMM: 256x128 CTA, m64n64 warp tile -------
// EPI 0: CoutH = A@B + bias (half)                  (qkv)
// EPI 1: CoutF[map(r)] = resid[map(r)] + v (fp32)   (proj + reverse + shortcut)
// EPI 2: CoutH = gelu(A@B + bias) (half)            (mlp1)
// EPI 3: CoutF[r*N+c] += v + bias (fp32)            (mlp2 residual into d_out)
#define BM 256
#define BN 128
#define BKT 16
#define STAGES 3

__device__ __forceinline__ void mma_f16(float c[4], const unsigned a[4], const unsigned b[2]) {
    asm volatile(
        "mma.sync.aligned.m16n8k16.row.col.f32.f16.f16.f32 "
        "{%0,%1,%2,%3}, {%4,%5,%6,%7}, {%8,%9}, {%0,%1,%2,%3};"
        : "+f"(c[0]), "+f"(c[1]), "+f"(c[2]), "+f"(c[3])
        : "r"(a[0]), "r"(a[1]), "r"(a[2]), "r"(a[3]), "r"(b[0]), "r"(b[1]));
}
__device__ __forceinline__ void cp16(unsigned dst, const void* src) {
    asm volatile("cp.async.cg.shared.global [%0], [%1], 16;" :: "r"(dst), "l"(src));
}
__device__ __forceinline__ void ldsm_x4(unsigned r[4], unsigned addr) {
    asm volatile("ldmatrix.sync.aligned.m8n8.x4.shared.b16 {%0,%1,%2,%3}, [%4];"
        : "=r"(r[0]), "=r"(r[1]), "=r"(r[2]), "=r"(r[3]) : "r"(addr));
}
__device__ __forceinline__ void ldsm_x4_t(unsigned& r0, unsigned& r1, unsigned& r2, unsigned& r3, unsigned addr) {
    asm volatile("ldmatrix.sync.aligned.m8n8.x4.trans.shared.b16 {%0,%1,%2,%3}, [%4];"
        : "=r"(r0), "=r"(r1), "=r"(r2), "=r"(r3) : "r"(addr));
}

template<int EPI>
__global__ void __launch_bounds__(256) hgemm_kernel(
    const __half* __restrict__ A, const __half* __restrict__ Bm,
    const float* __restrict__ bias, float* __restrict__ CoutF,
    __half* __restrict__ CoutH, const float* __restrict__ resid,
    int M, int N, int K)
{
    // A stage: [256 m][2 chunks of 16B], swizzle chunk^((m>>2)&1)   (8KB/stage)
    // B stage: [16 k][16 chunks of 16B], swizzle chunk^(k&7)        (4KB/stage)
    __shared__ uint4 As[STAGES][512];
    __shared__ uint4 Bs[STAGES][256];

    int tid  = threadIdx.x;
    int lane = tid & 31, warp = tid >> 5;
    int wm = warp & 3, wn = warp >> 2;    // 4 warps along M (64 rows each), 2 along N (64 cols)
    int g = lane >> 2, kq = lane & 3;
    int row0 = blockIdx.y * BM, col0 = blockIdx.x * BN;

    unsigned As_base = (unsigned)__cvta_generic_to_shared(&As[0][0]);
    unsigned Bs_base = (unsigned)__cvta_generic_to_shared(&Bs[0][0]);

    float acc[4][8][4];
    #pragma unroll
    for (int mt = 0; mt < 4; mt++)
        #pragma unroll
        for (int nt = 0; nt < 8; nt++)
            #pragma unroll
            for (int i = 0; i < 4; i++) acc[mt][nt][i] = 0.0f;

    // cp.async loader assignment: each thread loads 2 A rows + 1 B row-chunk
    int am = tid >> 1;                 // 0..127 -> rows am, am+128
    int ac = tid & 1;                  // A k-chunk
    unsigned a_sm = (unsigned)((am * 2 + (ac ^ ((am >> 2) & 1))) * 16);   // +4096 for row am+128
    const __half* agp  = A + (size_t)(row0 + am) * K + ac * 8;
    const __half* agp2 = agp + (size_t)128 * K;
    int bk = tid >> 4;                 // 0..15
    int bc = tid & 15;                 // B n-chunk
    unsigned b_sm = (unsigned)((bk * 16 + (bc ^ (bk & 7))) * 16);
    const __half* bgp = Bm + (size_t)bk * N + col0 + bc * 8;

    const int niter = K / BKT;

    // prologue: stages 0..STAGES-2
    #pragma unroll
    for (int s = 0; s < STAGES - 1; s++) {
        cp16(As_base + s * 8192 + a_sm, agp + s * BKT);
        cp16(As_base + s * 8192 + a_sm + 4096, agp2 + s * BKT);
        cp16(Bs_base + s * 4096 + b_sm, bgp + (size_t)s * BKT * N);
        asm volatile("cp.async.commit_group;");
    }
    asm volatile("cp.async.wait_group %0;" :: "n"(STAGES - 2) : "memory");
    __syncthreads();

    // ldmatrix lane addressing
    int sel = lane >> 3;                       // 0..3
    int l8  = lane & 7;
    int a_lrow_off = l8 + (sel & 1) * 8;
    int a_ch = sel >> 1;
    int b_lk = l8 + (sel & 1) * 8;
    int b_choff = sel >> 1;

    int s = 0, sn = STAGES - 1;
    for (int kt = 0; kt < niter; kt++) {
        int kn = kt + STAGES - 1;
        if (kn < niter) {
            cp16(As_base + sn * 8192 + a_sm, agp + kn * BKT);
            cp16(As_base + sn * 8192 + a_sm + 4096, agp2 + kn * BKT);
            cp16(Bs_base + sn * 4096 + b_sm, bgp + (size_t)kn * BKT * N);
        }
        asm volatile("cp.async.commit_group;");

        unsigned a[4][4], b[8][2];
        unsigned a_base = As_base + s * 8192;
        unsigned b_base = Bs_base + s * 4096;
        #pragma unroll
        for (int mt = 0; mt < 4; mt++) {
            int lrow = wm * 64 + mt * 16 + a_lrow_off;
            unsigned addr = a_base + (unsigned)((lrow * 2 + (a_ch ^ ((lrow >> 2) & 1))) * 16);
            ldsm_x4(a[mt], addr);
        }
        #pragma unroll
        for (int p = 0; p < 4; p++) {
            int ch = wn * 8 + p * 2 + b_choff;
            unsigned addr = b_base + (unsigned)((b_lk * 16 + (ch ^ (b_lk & 7))) * 16);
            ldsm_x4_t(b[2 * p][0], b[2 * p][1], b[2 * p + 1][0], b[2 * p + 1][1], addr);
        }
        #pragma unroll
        for (int mt = 0; mt < 4; mt++)
            #pragma unroll
            for (int nt = 0; nt < 8; nt++)
                mma_f16(acc[mt][nt], a[mt], b[nt]);

        asm volatile("cp.async.wait_group %0;" :: "n"(STAGES - 2) : "memory");
        __syncthreads();
        // FIX (R11 bug): compute stage advances by 1 each iteration, NOT jump to sn.
        s = s + 1;  if (s == STAGES)  s = 0;
        sn = sn + 1; if (sn == STAGES) sn = 0;
    }

    // epilogue: thread (g,kq) owns rows (+g, +g+8), cols kq*2, kq*2+1 per 8-col tile
    #pragma unroll
    for (int mt = 0; mt < 4; mt++) {
        int r_lo = row0 + wm * 64 + mt * 16 + g;
        int r_hi = r_lo + 8;
        size_t dlo = 0, dhi = 0;
        if (EPI == 1) {
            dlo = (size_t)win_row_to_src(r_lo) * CC;
            dhi = (size_t)win_row_to_src(r_hi) * CC;
        }
        #pragma unroll
        for (int nt = 0; nt < 8; nt++) {
            int c = col0 + wn * 64 + nt * 8 + kq * 2;
            float bs0 = bias[c], bs1 = bias[c + 1];
            float v0 = acc[mt][nt][0] + bs0;
            float v1 = acc[mt][nt][1] + bs1;
            float v2 = acc[mt][nt][2] + bs0;
            float v3 = acc[mt][nt][3] + bs1;
            if (EPI == 0) {
                *(__half2*)&CoutH[(size_t)r_lo * N + c] = __floats2half2_rn(v0, v1);
                *(__half2*)&CoutH[(size_t)r_hi * N + c] = __floats2half2_rn(v2, v3);
            } else if (EPI == 1) {
                CoutF[dlo + c]     = resid[dlo + c]     + v0;
                CoutF[dlo + c + 1] = resid[dlo + c + 1] + v1;
                CoutF[dhi + c]     = resid[dhi + c]     + v2;
                CoutF[dhi + c + 1] = resid[dhi + c + 1] + v3;
            } else if (EPI == 2) {
                const float is2 = 0.7071067811865476f;
                float g0 = 0.5f * v0 * (1.0f + erff(v0 * is2));
                float g1v = 0.5f * v1 * (1.0f + erff(v1 * is2));
                float g2v = 0.5f * v2 * (1.0f + erff(v2 * is2));
                float g3 = 0.5f * v3 * (1.0f + erff(v3 * is2));
                *(__half2*)&CoutH[(size_t)r_lo * N + c] = __floats2half2_rn(g0, g1v);
                *(__half2*)&CoutH[(size_t)r_hi * N + c] = __floats2half2_rn(g2v, g3);
            } else {  // EPI == 3
                size_t o = (size_t)r_lo * N + c;
                CoutF[o]     += v0;
                CoutF[o + 1] += v1;
                size_t o2 = (size_t)r_hi * N + c;
                CoutF[o2]     += v2;
                CoutF[o2 + 1] += v3;
            }
        }
    }
}

// ---------------- windowed attention (fp16 in/out, fp32 math) ----------------
__global__ void __launch_bounds__(256) attn_kernel(
    const __half* __restrict__ qkv, const float* __restrict__ rpb,
    __half* __restrict__ out)
{
    int blk = blockIdx.x;
    int w = blk / NHEAD, head = blk - w * NHEAD;
    int wi = w & (NWIN - 1);
    int wh = wi >> 3, ww = wi & 7;

    __shared__ float q[NTOK * HD];
    __shared__ float k[NTOK * HD];
    __shared__ float v[NTOK * HD];
    __shared__ float at[NTOK * 52];

    int tid = threadIdx.x;
    size_t base = (size_t)w * NTOK * (3 * CC) + head * HD;
    const float scale = 0.17677669529663687f;
    for (int i = tid; i < NTOK * HD; i += 256) {
        int n = i >> 5, d = i & 31;
        size_t o = base + (size_t)n * (3 * CC) + d;
        q[i] = __half2float(qkv[o]) * scale;
        k[i] = __half2float(qkv[o + CC]);
        v[i] = __half2float(qkv[o + 2 * CC]);
    }
    __syncthreads();

    for (int e = tid; e < NTOK * NTOK; e += 256) {
        int n = e / NTOK, m = e - n * NTOK;
        float s = 0.0f;
        #pragma unroll
        for (int d = 0; d < HD; d++) s = fmaf(q[n * HD + d], k[m * HD + d], s);
        int r1 = n / WS, c1 = n - r1 * WS;
        int r2 = m / WS, c2 = m - r2 * WS;
        int idx = (r1 - r2 + WS - 1) * (2 * WS - 1) + (c1 - c2 + WS - 1);
        s += rpb[idx * NHEAD + head];
        int gh1 = wh * WS + r1, gw1 = ww * WS + c1;
        int gh2 = wh * WS + r2, gw2 = ww * WS + c2;
        int id1 = (gh1 < 49 ? 0 : (gh1 < 53 ? 1 : 2)) * 3 + (gw1 < 49 ? 0 : (gw1 < 53 ? 1 : 2));
        int id2 = (gh2 < 49 ? 0 : (gh2 < 53 ? 1 : 2)) * 3 + (gw2 < 49 ? 0 : (gw2 < 53 ? 1 : 2));
        if (id1 != id2) s -= 100.0f;
        at[n * 52 + m] = s;
    }
    __syncthreads();

    if (tid < NTOK) {
        float mx = -1e30f;
        for (int m2 = 0; m2 < NTOK; m2++) mx = fmaxf(mx, at[tid * 52 + m2]);
        float sum = 0.0f;
        for (int m2 = 0; m2 < NTOK; m2++) {
            float e2 = __expf(at[tid * 52 + m2] - mx);
            at[tid * 52 + m2] = e2;
            sum += e2;
        }
        float inv = 1.0f / sum;
        for (int m2 = 0; m2 < NTOK; m2++) at[tid * 52 + m2] *= inv;
    }
    __syncthreads();

    for (int i = tid; i < NTOK * HD; i += 256) {
        int n = i >> 5, d = i & 31;
        float s = 0.0f;
        #pragma unroll
        for (int m2 = 0; m2 < NTOK; m2++) s = fmaf(at[n * 52 + m2], v[m2 * HD + d], s);
        out[(size_t)(w * NTOK + n) * CC + head * HD + d] = __float2half(s);
    }
}

// ---------------- launch ----------------
extern "C" void kernel_launch(void* const* d_in, const int* in_sizes, int n_in,
                              void* d_out, int out_size)
{
    const float* x      = (const float*)d_in[0];
    const float* g1     = (const float*)d_in[1];
    const float* b1     = (const float*)d_in[2];
    const float* w_qkv  = (const float*)d_in[3];
    const float* b_qkv  = (const float*)d_in[4];
    const float* w_proj = (const float*)d_in[5];
    const float* b_proj = (const float*)d_in[6];
    const float* rpb    = (const float*)d_in[7];
    const float* g2     = (const float*)d_in[8];
    const float* b2     = (const float*)d_in[9];
    const float* w1     = (const float*)d_in[10];
    const float* bm1    = (const float*)d_in[11];
    const float* w2     = (const float*)d_in[12];
    const float* bm2    = (const float*)d_in[13];
    float* out = (float*)d_out;

    static __half *p_hwin = nullptr, *p_qkv = nullptr, *p_attn = nullptr,
                  *p_h2 = nullptr, *p_hid = nullptr,
                  *p_wqkv = nullptr, *p_wproj = nullptr, *p_w1 = nullptr, *p_w2 = nullptr;
    if (!p_hwin) {
        cudaGetSymbolAddress((void**)&p_hwin,  g_hwin);
        cudaGetSymbolAddress((void**)&p_qkv,   g_qkv);
        cudaGetSymbolAddress((void**)&p_attn,  g_attn);
        cudaGetSymbolAddress((void**)&p_h2,    g_h2);
        cudaGetSymbolAddress((void**)&p_hid,   g_hid);
        cudaGetSymbolAddress((void**)&p_wqkv,  g_wqkv);
        cudaGetSymbolAddress((void**)&p_wproj, g_wproj);
        cudaGetSymbolAddress((void**)&p_w1,    g_w1);
        cudaGetSymbolAddress((void**)&p_w2,    g_w2);
    }

    // 0. weight conversions (tiny)
    f2h_kernel<<<(CC * 3 * CC) / 4 / 256, 256>>>(w_qkv, p_wqkv, CC * 3 * CC);
    f2h_kernel<<<(CC * CC) / 4 / 256, 256>>>(w_proj, p_wproj, CC * CC);
    f2h_kernel<<<(CC * HID) / 4 / 256, 256>>>(w1, p_w1, CC * HID);
    f2h_kernel<<<(HID * CC) / 4 / 256, 256>>>(w2, p_w2, HID * CC);

    // 1. LN1 + roll + window partition -> half
    ln_kernel<true><<<MROWS, 128>>>(x, g1, b1, p_hwin);
    // 2. QKV GEMM  [100352,384] @ [384,1152] -> half
    hgemm_kernel<0><<<dim3(9, MROWS / BM), 256>>>(p_hwin, p_wqkv, b_qkv, nullptr, p_qkv, nullptr, MROWS, 3 * CC, CC);
    // 3. windowed attention -> half
    attn_kernel<<<BNW * NHEAD, 256>>>(p_qkv, rpb, p_attn);
    // 4. proj GEMM + window reverse + unshift + shortcut residual -> fp32 d_out
    hgemm_kernel<1><<<dim3(3, MROWS / BM), 256>>>(p_attn, p_wproj, b_proj, out, nullptr, x, MROWS, CC, CC);
    // 5. LN2 -> half
    ln_kernel<false><<<MROWS, 128>>>(out, g2, b2, p_h2);
    // 6. MLP1 + GELU  [100352,384] @ [384,1536] -> half
    hgemm_kernel<2><<<dim3(12, MROWS / BM), 256>>>(p_h2, p_w1, bm1, nullptr, p_hid, nullptr, MROWS, HID, CC);
    // 7. MLP2 + residual into fp32 d_out  [100352,1536] @ [1536,384]
    hgemm_kernel<3><<<dim3(3, MROWS / BM), 256>>>(p_hid, p_w2, bm2, out, nullptr, nullptr, MROWS, CC, HID);
}

// round 16
// speedup vs baseline: 1.0573x; 1.0573x over previous
#include <cuda_runtime.h>
#include <cuda_fp16.h>
#include <math.h>

// ---------------- problem constants ----------------
#define BATCH 32
#define HH 56
#define WW_ 56
#define CC 384
#define NHEAD 12
#define WS 7
#define SS 3
#define NTOK 49
#define HID 1536
#define NWIN 64
#define HD 32
#define BNW 2048
#define MROWS 100352         // divisible by 128

// ---------------- scratch (device globals; no allocs) ----------------
__device__ __align__(16) __half g_hwin[(size_t)MROWS * CC];
__device__ __align__(16) __half g_qkv [(size_t)MROWS * 3 * CC];
__device__ __align__(16) __half g_attn[(size_t)MROWS * CC];
__device__ __align__(16) __half g_h2  [(size_t)MROWS * CC];
__device__ __align__(16) __half g_hid [(size_t)MROWS * HID];
__device__ __align__(16) __half g_wqkv [CC * 3 * CC];
__device__ __align__(16) __half g_wproj[CC * CC];
__device__ __align__(16) __half g_w1   [CC * HID];
__device__ __align__(16) __half g_w2   [HID * CC];

__device__ __forceinline__ int win_row_to_src(int r) {
    int b   = r / (NWIN * NTOK);
    int rem = r - b * (NWIN * NTOK);
    int wi  = rem / NTOK;
    int t   = rem - wi * NTOK;
    int wh = wi >> 3, ww = wi & 7;
    int th = t / WS,  tw = t - th * WS;
    int h = wh * WS + th + SS; if (h >= HH)  h -= HH;
    int w = ww * WS + tw + SS; if (w >= WW_) w -= WW_;
    return b * (HH * WW_) + h * WW_ + w;
}

// ---------------- fp32 -> fp16 weight conversion ----------------
__global__ void f2h_kernel(const float* __restrict__ s, __half* __restrict__ d, int n) {
    int i = (blockIdx.x * blockDim.x + threadIdx.x) * 4;
    if (i < n) {
        float4 v = *(const float4*)(s + i);
        __half2* p = (__half2*)(d + i);
        p[0] = __floats2half2_rn(v.x, v.y);
        p[1] = __floats2half2_rn(v.z, v.w);
    }
}

// ---------------- LayerNorm (fp32 in, fp16 out; optional window gather) ------
template<bool GATHER>
__global__ void __launch_bounds__(128) ln_kernel(
    const float* __restrict__ xin, const float* __restrict__ gamma,
    const float* __restrict__ beta, __half* __restrict__ out)
{
    int row = blockIdx.x;
    int src = GATHER ? win_row_to_src(row) : row;
    const float* xr = xin + (size_t)src * CC;
    int t = threadIdx.x;
    float v0 = xr[t], v1 = xr[t + 128], v2 = xr[t + 256];
    float s  = v0 + v1 + v2;
    float ss = v0 * v0 + v1 * v1 + v2 * v2;
    __shared__ float sh[16];
    #pragma unroll
    for (int o = 16; o; o >>= 1) {
        s  += __shfl_down_sync(0xffffffffu, s,  o);
        ss += __shfl_down_sync(0xffffffffu, ss, o);
    }
    int warp = t >> 5, lane = t & 31;
    if (lane == 0) { sh[warp] = s; sh[warp + 4] = ss; }
    __syncthreads();
    if (t == 0) {
        float S  = sh[0] + sh[1] + sh[2] + sh[3];
        float Q  = sh[4] + sh[5] + sh[6] + sh[7];
        float m  = S * (1.0f / CC);
        float var = Q * (1.0f / CC) - m * m;
        sh[8] = m; sh[9] = rsqrtf(var + 1e-5f);
    }
    __syncthreads();
    float m = sh[8], rinv = sh[9];
    __half* orow = out + (size_t)row * CC;
    orow[t]       = __float2half((v0 - m) * rinv * gamma[t]       + beta[t]);
    orow[t + 128] = __float2half((v1 - m) * rinv * gamma[t + 128] + beta[t + 128]);
    orow[t + 256] = __float2half((v2 - m) * rinv * gamma[t + 256] + beta[t + 256]);
}

// ------- fp16 mma.sync GEMM: 128x64 CTA, m32n32 warp tile, 3 CTAs/SM --------
#define BM 128
#define BN 64
#define BKT 16
#define STAGES 4

__device__ __forceinline__ void mma_f16(float c[4], const unsigned a[4], const unsigned b[2]) {
    asm volatile(
        "mma.sync.aligned.m16n8k16.row.col.f32.f16.f16.f32 "
        "{%0,%1,%2,%3}, {%4,%5,%6,%7}, {%8,%9}, {%0,%1,%2,%3};"
        : "+f"(c[0]), "+f"(c[1]), "+f"(c[2]), "+f"(c[3])
        : "r"(a[0]), "r"(a[1]), "r"(a[2]), "r"(a[3]), "r"(b[0]), "r"(b[1]));
}
__device__ __forceinline__ void cp16(unsigned dst, const void* src) {
    asm volatile("cp.async.cg.shared.global [%0], [%1], 16;" :: "r"(dst), "l"(src));
}
__device__ __forceinline__ void ldsm_x4(unsigned r[4], unsigned addr) {
    asm volatile("ldmatrix.sync.aligned.m8n8.x4.shared.b16 {%0,%1,%2,%3}, [%4];"
        : "=r"(r[0]), "=r"(r[1]), "=r"(r[2]), "=r"(r[3]) : "r"(addr));
}
__device__ __forceinline__ void ldsm_x4_t(unsigned& r0, unsigned& r1, unsigned& r2, unsigned& r3, unsigned addr) {
    asm volatile("ldmatrix.sync.aligned.m8n8.x4.trans.shared.b16 {%0,%1,%2,%3}, [%4];"
        : "=r"(r0), "=r"(r1), "=r"(r2), "=r"(r3) : "r"(addr));
}

template<int EPI>
__global__ void __launch_bounds__(256, 3) hgemm_kernel(
    const __half* __restrict__ A, const __half* __restrict__ Bm,
    const float* __restrict__ bias, float* __restrict__ CoutF,
    __half* __restrict__ CoutH, const float* __restrict__ resid,
    int M, int N, int K)
{
    __shared__ uint4 As[STAGES][256];   // [128 m][2 chunks], chunk^((m>>2)&1)
    __shared__ uint4 Bs[STAGES][128];   // [16 k][8 chunks],  chunk^(k&7)

    int tid  = threadIdx.x;
    int lane = tid & 31, warp = tid >> 5;
    int wm = warp & 3, wn = warp >> 2;
    int g = lane >> 2, kq = lane & 3;
    int row0 = blockIdx.y * BM, col0 = blockIdx.x * BN;

    unsigned As_base = (unsigned)__cvta_generic_to_shared(&As[0][0]);
    unsigned Bs_base = (unsigned)__cvta_generic_to_shared(&Bs[0][0]);

    float acc[2][4][4];
    #pragma unroll
    for (int mt = 0; mt < 2; mt++)
        #pragma unroll
        for (int nt = 0; nt < 4; nt++)
            #pragma unroll
            for (int i = 0; i < 4; i++) acc[mt][nt][i] = 0.0f;

    int am = tid >> 1;
    int ac = tid & 1;
    unsigned a_sm = (unsigned)((am * 2 + (ac ^ ((am >> 2) & 1))) * 16);
    const __half* agp = A + (size_t)(row0 + am) * K + ac * 8;
    int bk = (tid & 127) >> 3;
    int bc = tid & 7;
    unsigned b_sm = (unsigned)((bk * 8 + (bc ^ (bk & 7))) * 16);
    const __half* bgp = Bm + (size_t)bk * N + col0 + bc * 8;
    bool do_b = tid < 128;

    const int niter = K / BKT;

    #pragma unroll
    for (int s = 0; s < STAGES - 1; s++) {
        cp16(As_base + s * 4096 + a_sm, agp + s * BKT);
        if (do_b) cp16(Bs_base + s * 2048 + b_sm, bgp + (size_t)s * BKT * N);
        asm volatile("cp.async.commit_group;");
    }
    asm volatile("cp.async.wait_group %0;" :: "n"(STAGES - 2) : "memory");
    __syncthreads();

    int sel = lane >> 3;
    int l8  = lane & 7;
    int a_lrow_off = l8 + (sel & 1) * 8;
    int a_ch = sel >> 1;
    int b_lk = l8 + (sel & 1) * 8;
    int b_choff = sel >> 1;

    for (int kt = 0; kt < niter; kt++) {
        int s = kt & (STAGES - 1);
        int kn = kt + STAGES - 1;
        if (kn < niter) {
            int sn = kn & (STAGES - 1);
            cp16(As_base + sn * 4096 + a_sm, agp + kn * BKT);
            if (do_b) cp16(Bs_base + sn * 2048 + b_sm, bgp + (size_t)kn * BKT * N);
        }
        asm volatile("cp.async.commit_group;");

        unsigned a[2][4], b[4][2];
        unsigned a_base = As_base + s * 4096;
        unsigned b_base = Bs_base + s * 2048;
        #pragma unroll
        for (int mt = 0; mt < 2; mt++) {
            int lrow = wm * 32 + mt * 16 + a_lrow_off;
            unsigned addr = a_base + (unsigned)((lrow * 2 + (a_ch ^ ((lrow >> 2) & 1))) * 16);
            ldsm_x4(a[mt], addr);
        }
        #pragma unroll
        for (int p = 0; p < 2; p++) {
            int ch = wn * 4 + p * 2 + b_choff;
            unsigned addr = b_base + (unsigned)((b_lk * 8 + (ch ^ (b_lk & 7))) * 16);
            ldsm_x4_t(b[2 * p][0], b[2 * p][1], b[2 * p + 1][0], b[2 * p + 1][1], addr);
        }
        #pragma unroll
        for (int mt = 0; mt < 2; mt++)
            #pragma unroll
            for (int nt = 0; nt < 4; nt++)
                mma_f16(acc[mt][nt], a[mt], b[nt]);

        asm volatile("cp.async.wait_group %0;" :: "n"(STAGES - 2) : "memory");
        __syncthreads();
    }

    #pragma unroll
    for (int mt = 0; mt < 2; mt++) {
        int r_lo = row0 + wm * 32 + mt * 16 + g;
        int r_hi = r_lo + 8;
        size_t dlo = 0, dhi = 0;
        if (EPI == 1) {
            dlo = (size_t)win_row_to_src(r_lo) * CC;
            dhi = (size_t)win_row_to_src(r_hi) * CC;
        }
        #pragma unroll
        for (int nt = 0; nt < 4; nt++) {
            int c = col0 + wn * 32 + nt * 8 + kq * 2;
            float bs0 = bias[c], bs1 = bias[c + 1];
            float v0 = acc[mt][nt][0] + bs0;
            float v1 = acc[mt][nt][1] + bs1;
            float v2 = acc[mt][nt][2] + bs0;
            float v3 = acc[mt][nt][3] + bs1;
            if (EPI == 0) {
                *(__half2*)&CoutH[(size_t)r_lo * N + c] = __floats2half2_rn(v0, v1);
                *(__half2*)&CoutH[(size_t)r_hi * N + c] = __floats2half2_rn(v2, v3);
            } else if (EPI == 1) {
                CoutF[dlo + c]     = resid[dlo + c]     + v0;
                CoutF[dlo + c + 1] = resid[dlo + c + 1] + v1;
                CoutF[dhi + c]     = resid[dhi + c]     + v2;
                CoutF[dhi + c + 1] = resid[dhi + c + 1] + v3;
            } else if (EPI == 2) {
                const float is2 = 0.7071067811865476f;
                float g0 = 0.5f * v0 * (1.0f + erff(v0 * is2));
                float g1v = 0.5f * v1 * (1.0f + erff(v1 * is2));
                float g2v = 0.5f * v2 * (1.0f + erff(v2 * is2));
                float g3 = 0.5f * v3 * (1.0f + erff(v3 * is2));
                *(__half2*)&CoutH[(size_t)r_lo * N + c] = __floats2half2_rn(g0, g1v);
                *(__half2*)&CoutH[(size_t)r_hi * N + c] = __floats2half2_rn(g2v, g3);
            } else {
                size_t o = (size_t)r_lo * N + c;
                CoutF[o]     += v0;
                CoutF[o + 1] += v1;
                size_t o2 = (size_t)r_hi * N + c;
                CoutF[o2]     += v2;
                CoutF[o2 + 1] += v3;
            }
        }
    }
}

// ---------------- windowed attention (fp16 in/out, fp32 math) ----------------
__global__ void __launch_bounds__(256) attn_kernel(
    const __half* __restrict__ qkv, const float* __restrict__ rpb,
    __half* __restrict__ out)
{
    int blk = blockIdx.x;
    int w = blk / NHEAD, head = blk - w * NHEAD;
    int wi = w & (NWIN - 1);
    int wh = wi >> 3, ww = wi & 7;

    __shared__ float q[NTOK * HD];
    __shared__ float k[NTOK * HD];
    __shared__ float v[NTOK * HD];
    __shared__ float at[NTOK * 52];

    int tid = threadIdx.x;
    size_t base = (size_t)w * NTOK * (3 * CC) + head * HD;
    const float scale = 0.17677669529663687f;
    for (int i = tid; i < NTOK * HD; i += 256) {
        int n = i >> 5, d = i & 31;
        size_t o = base + (size_t)n * (3 * CC) + d;
        q[i] = __half2float(qkv[o]) * scale;
        k[i] = __half2float(qkv[o + CC]);
        v[i] = __half2float(qkv[o + 2 * CC]);
    }
    __syncthreads();

    for (int e = tid; e < NTOK * NTOK; e += 256) {
        int n = e / NTOK, m = e - n * NTOK;
        float s = 0.0f;
        #pragma unroll
        for (int d = 0; d < HD; d++) s = fmaf(q[n * HD + d], k[m * HD + d], s);
        int r1 = n / WS, c1 = n - r1 * WS;
        int r2 = m / WS, c2 = m - r2 * WS;
        int idx = (r1 - r2 + WS - 1) * (2 * WS - 1) + (c1 - c2 + WS - 1);
        s += rpb[idx * NHEAD + head];
        int gh1 = wh * WS + r1, gw1 = ww * WS + c1;
        int gh2 = wh * WS + r2, gw2 = ww * WS + c2;
        int id1 = (gh1 < 49 ? 0 : (gh1 < 53 ? 1 : 2)) * 3 + (gw1 < 49 ? 0 : (gw1 < 53 ? 1 : 2));
        int id2 = (gh2 < 49 ? 0 : (gh2 < 53 ? 1 : 2)) * 3 + (gw2 < 49 ? 0 : (gw2 < 53 ? 1 : 2));
        if (id1 != id2) s -= 100.0f;
        at[n * 52 + m] = s;
    }
    __syncthreads();

    if (tid < NTOK) {
        float mx = -1e30f;
        for (int m2 = 0; m2 < NTOK; m2++) mx = fmaxf(mx, at[tid * 52 + m2]);
        float sum = 0.0f;
        for (int m2 = 0; m2 < NTOK; m2++) {
            float e2 = __expf(at[tid * 52 + m2] - mx);
            at[tid * 52 + m2] = e2;
            sum += e2;
        }
        float inv = 1.0f / sum;
        for (int m2 = 0; m2 < NTOK; m2++) at[tid * 52 + m2] *= inv;
    }
    __syncthreads();

    for (int i = tid; i < NTOK * HD; i += 256) {
        int n = i >> 5, d = i & 31;
        float s = 0.0f;
        #pragma unroll
        for (int m2 = 0; m2 < NTOK; m2++) s = fmaf(at[n * 52 + m2], v[m2 * HD + d], s);
        out[(size_t)(w * NTOK + n) * CC + head * HD + d] = __float2half(s);
    }
}

// ---------------- launch ----------------
extern "C" void kernel_launch(void* const* d_in, const int* in_sizes, int n_in,
                              void* d_out, int out_size)
{
    const float* x      = (const float*)d_in[0];
    const float* g1     = (const float*)d_in[1];
    const float* b1     = (const float*)d_in[2];
    const float* w_qkv  = (const float*)d_in[3];
    const float* b_qkv  = (const float*)d_in[4];
    const float* w_proj = (const float*)d_in[5];
    const float* b_proj = (const float*)d_in[6];
    const float* rpb    = (const float*)d_in[7];
    const float* g2     = (const float*)d_in[8];
    const float* b2     = (const float*)d_in[9];
    const float* w1     = (const float*)d_in[10];
    const float* bm1    = (const float*)d_in[11];
    const float* w2     = (const float*)d_in[12];
    const float* bm2    = (const float*)d_in[13];
    float* out = (float*)d_out;

    static __half *p_hwin = nullptr, *p_qkv = nullptr, *p_attn = nullptr,
                  *p_h2 = nullptr, *p_hid = nullptr,
                  *p_wqkv = nullptr, *p_wproj = nullptr, *p_w1 = nullptr, *p_w2 = nullptr;
    if (!p_hwin) {
        cudaGetSymbolAddress((void**)&p_hwin,  g_hwin);
        cudaGetSymbolAddress((void**)&p_qkv,   g_qkv);
        cudaGetSymbolAddress((void**)&p_attn,  g_attn);
        cudaGetSymbolAddress((void**)&p_h2,    g_h2);
        cudaGetSymbolAddress((void**)&p_hid,   g_hid);
        cudaGetSymbolAddress((void**)&p_wqkv,  g_wqkv);
        cudaGetSymbolAddress((void**)&p_wproj, g_wproj);
        cudaGetSymbolAddress((void**)&p_w1,    g_w1);
        cudaGetSymbolAddress((void**)&p_w2,    g_w2);
    }

    // 0. weight conversions (tiny)
    f2h_kernel<<<(CC * 3 * CC) / 4 / 256, 256>>>(w_qkv, p_wqkv, CC * 3 * CC);
    f2h_kernel<<<(CC * CC) / 4 / 256, 256>>>(w_proj, p_wproj, CC * CC);
    f2h_kernel<<<(CC * HID) / 4 / 256, 256>>>(w1, p_w1, CC * HID);
    f2h_kernel<<<(HID * CC) / 4 / 256, 256>>>(w2, p_w2, HID * CC);

    // 1. LN1 + roll + window partition -> half
    ln_kernel<true><<<MROWS, 128>>>(x, g1, b1, p_hwin);
    // 2. QKV GEMM  [100352,384] @ [384,1152] -> half
    hgemm_kernel<0><<<dim3(1152 / BN, MROWS / BM), 256>>>(p_hwin, p_wqkv, b_qkv, nullptr, p_qkv, nullptr, MROWS, 3 * CC, CC);
    // 3. windowed attention -> half
    attn_kernel<<<BNW * NHEAD, 256>>>(p_qkv, rpb, p_attn);
    // 4. proj GEMM + window reverse + unshift + shortcut residual -> fp32 d_out
    hgemm_kernel<1><<<dim3(CC / BN, MROWS / BM), 256>>>(p_attn, p_wproj, b_proj, out, nullptr, x, MROWS, CC, CC);
    // 5. LN2 -> half
    ln_kernel<false><<<MROWS, 128>>>(out, g2, b2, p_h2);
    // 6. MLP1 + GELU  [100352,384] @ [384,1536] -> half
    hgemm_kernel<2><<<dim3(HID / BN, MROWS / BM), 256>>>(p_h2, p_w1, bm1, nullptr, p_hid, nullptr, MROWS, HID, CC);
    // 7. MLP2 + residual into fp32 d_out  [100352,1536] @ [1536,384]
    hgemm_kernel<3><<<dim3(CC / BN, MROWS / BM), 256>>>(p_hid, p_w2, bm2, out, nullptr, nullptr, MROWS, CC, HID);
}

// round 17
// speedup vs baseline: 1.0692x; 1.0112x over previous
#include <cuda_runtime.h>
#include <cuda_fp16.h>
#include <math.h>

// ---------------- problem constants ----------------
#define BATCH 32
#define HH 56
#define WW_ 56
#define CC 384
#define NHEAD 12
#define WS 7
#define SS 3
#define NTOK 49
#define HID 1536
#define NWIN 64
#define HD 32
#define BNW 2048
#define MROWS 100352         // divisible by 128

// ---------------- scratch (device globals; no allocs) ----------------
__device__ __align__(16) __half g_hwin[(size_t)MROWS * CC];
__device__ __align__(16) __half g_qkv [(size_t)MROWS * 3 * CC];
__device__ __align__(16) __half g_attn[(size_t)MROWS * CC];
__device__ __align__(16) __half g_h2  [(size_t)MROWS * CC];
__device__ __align__(16) __half g_hid [(size_t)MROWS * HID];
__device__ __align__(16) __half g_wqkv [CC * 3 * CC];
__device__ __align__(16) __half g_wproj[CC * CC];
__device__ __align__(16) __half g_w1   [CC * HID];
__device__ __align__(16) __half g_w2   [HID * CC];

__device__ __forceinline__ int win_row_to_src(int r) {
    int b   = r / (NWIN * NTOK);
    int rem = r - b * (NWIN * NTOK);
    int wi  = rem / NTOK;
    int t   = rem - wi * NTOK;
    int wh = wi >> 3, ww = wi & 7;
    int th = t / WS,  tw = t - th * WS;
    int h = wh * WS + th + SS; if (h >= HH)  h -= HH;
    int w = ww * WS + tw + SS; if (w >= WW_) w -= WW_;
    return b * (HH * WW_) + h * WW_ + w;
}

// ---------------- fp32 -> fp16 weight conversion ----------------
__global__ void f2h_kernel(const float* __restrict__ s, __half* __restrict__ d, int n) {
    int i = (blockIdx.x * blockDim.x + threadIdx.x) * 4;
    if (i < n) {
        float4 v = *(const float4*)(s + i);
        __half2* p = (__half2*)(d + i);
        p[0] = __floats2half2_rn(v.x, v.y);
        p[1] = __floats2half2_rn(v.z, v.w);
    }
}

// ---------------- LayerNorm (fp32 in, fp16 out; optional window gather) ------
template<bool GATHER>
__global__ void __launch_bounds__(128) ln_kernel(
    const float* __restrict__ xin, const float* __restrict__ gamma,
    const float* __restrict__ beta, __half* __restrict__ out)
{
    int row = blockIdx.x;
    int src = GATHER ? win_row_to_src(row) : row;
    const float* xr = xin + (size_t)src * CC;
    int t = threadIdx.x;
    float v0 = xr[t], v1 = xr[t + 128], v2 = xr[t + 256];
    float s  = v0 + v1 + v2;
    float ss = v0 * v0 + v1 * v1 + v2 * v2;
    __shared__ float sh[16];
    #pragma unroll
    for (int o = 16; o; o >>= 1) {
        s  += __shfl_down_sync(0xffffffffu, s,  o);
        ss += __shfl_down_sync(0xffffffffu, ss, o);
    }
    int warp = t >> 5, lane = t & 31;
    if (lane == 0) { sh[warp] = s; sh[warp + 4] = ss; }
    __syncthreads();
    if (t == 0) {
        float S  = sh[0] + sh[1] + sh[2] + sh[3];
        float Q  = sh[4] + sh[5] + sh[6] + sh[7];
        float m  = S * (1.0f / CC);
        float var = Q * (1.0f / CC) - m * m;
        sh[8] = m; sh[9] = rsqrtf(var + 1e-5f);
    }
    __syncthreads();
    float m = sh[8], rinv = sh[9];
    __half* orow = out + (size_t)row * CC;
    orow[t]       = __float2half((v0 - m) * rinv * gamma[t]       + beta[t]);
    orow[t + 128] = __float2half((v1 - m) * rinv * gamma[t + 128] + beta[t + 128]);
    orow[t + 256] = __float2half((v2 - m) * rinv * gamma[t + 256] + beta[t + 256]);
}

// ---- fp16 mma.sync GEMM: 128x128 CTA, m32n64 warp tile, BKT=32 (2x16) ------
// EPI 0: CoutH = A@B + bias (half)                  (qkv)
// EPI 1: CoutF[map(r)] = resid[map(r)] + v (fp32)   (proj + reverse + shortcut)
// EPI 2: CoutH = gelu(A@B + bias) (half)            (mlp1)
// EPI 3: CoutF[r*N+c] += v + bias (fp32)            (mlp2 residual into d_out)
#define BM 128
#define BN 128
#define BKT 32
#define STAGES 3

__device__ __forceinline__ void mma_f16(float c[4], const unsigned a[4], const unsigned b[2]) {
    asm volatile(
        "mma.sync.aligned.m16n8k16.row.col.f32.f16.f16.f32 "
        "{%0,%1,%2,%3}, {%4,%5,%6,%7}, {%8,%9}, {%0,%1,%2,%3};"
        : "+f"(c[0]), "+f"(c[1]), "+f"(c[2]), "+f"(c[3])
        : "r"(a[0]), "r"(a[1]), "r"(a[2]), "r"(a[3]), "r"(b[0]), "r"(b[1]));
}
__device__ __forceinline__ void cp16(unsigned dst, const void* src) {
    asm volatile("cp.async.cg.shared.global [%0], [%1], 16;" :: "r"(dst), "l"(src));
}
__device__ __forceinline__ void ldsm_x4(unsigned r[4], unsigned addr) {
    asm volatile("ldmatrix.sync.aligned.m8n8.x4.shared.b16 {%0,%1,%2,%3}, [%4];"
        : "=r"(r[0]), "=r"(r[1]), "=r"(r[2]), "=r"(r[3]) : "r"(addr));
}
__device__ __forceinline__ void ldsm_x4_t(unsigned& r0, unsigned& r1, unsigned& r2, unsigned& r3, unsigned addr) {
    asm volatile("ldmatrix.sync.aligned.m8n8.x4.trans.shared.b16 {%0,%1,%2,%3}, [%4];"
        : "=r"(r0), "=r"(r1), "=r"(r2), "=r"(r3) : "r"(addr));
}

template<int EPI>
__global__ void __launch_bounds__(256) hgemm_kernel(
    const __half* __restrict__ A, const __half* __restrict__ Bm,
    const float* __restrict__ bias, float* __restrict__ CoutF,
    __half* __restrict__ CoutH, const float* __restrict__ resid,
    int M, int N, int K)
{
    // Each stage holds TWO 16-k sub-tiles in the proven R10 layout:
    // A sub-tile: [128 m][2 chunks of 16B], swizzle chunk^((m>>2)&1)   (4KB)
    // B sub-tile: [16 k][16 chunks of 16B], swizzle chunk^(k&7)        (4KB)
    __shared__ uint4 As[STAGES][2][256];
    __shared__ uint4 Bs[STAGES][2][256];

    int tid  = threadIdx.x;
    int lane = tid & 31, warp = tid >> 5;
    int wm = warp & 3, wn = warp >> 2;    // 4 warps along M, 2 along N
    int g = lane >> 2, kq = lane & 3;
    int row0 = blockIdx.y * BM, col0 = blockIdx.x * BN;

    unsigned As_base = (unsigned)__cvta_generic_to_shared(&As[0][0][0]);
    unsigned Bs_base = (unsigned)__cvta_generic_to_shared(&Bs[0][0][0]);

    float acc[2][8][4];
    #pragma unroll
    for (int mt = 0; mt < 2; mt++)
        #pragma unroll
        for (int nt = 0; nt < 8; nt++)
            #pragma unroll
            for (int i = 0; i < 4; i++) acc[mt][nt][i] = 0.0f;

    // loader assignment (per 16-k sub-tile, as in R10)
    int am = tid >> 1;                 // 0..127
    int ac = tid & 1;
    unsigned a_sm = (unsigned)((am * 2 + (ac ^ ((am >> 2) & 1))) * 16);
    const __half* agp = A + (size_t)(row0 + am) * K + ac * 8;
    int bk = tid >> 4;                 // 0..15
    int bc = tid & 15;
    unsigned b_sm = (unsigned)((bk * 16 + (bc ^ (bk & 7))) * 16);
    const __half* bgp = Bm + (size_t)bk * N + col0 + bc * 8;

    const int niter = K / BKT;         // 32-k tiles

    // prologue: stages 0..STAGES-2 (each = 2 sub-tiles)
    #pragma unroll
    for (int s = 0; s < STAGES - 1; s++) {
        #pragma unroll
        for (int h = 0; h < 2; h++) {
            int k0 = s * BKT + h * 16;
            cp16(As_base + (s * 2 + h) * 4096 + a_sm, agp + k0);
            cp16(Bs_base + (s * 2 + h) * 4096 + b_sm, bgp + (size_t)k0 * N);
        }
        asm volatile("cp.async.commit_group;");
    }
    asm volatile("cp.async.wait_group %0;" :: "n"(STAGES - 2) : "memory");
    __syncthreads();

    // ldmatrix lane addressing
    int sel = lane >> 3;
    int l8  = lane & 7;
    int a_lrow_off = l8 + (sel & 1) * 8;
    int a_ch = sel >> 1;
    int b_lk = l8 + (sel & 1) * 8;
    int b_choff = sel >> 1;

    for (int kt = 0; kt < niter; kt++) {
        int s = kt % STAGES;
        int kn = kt + STAGES - 1;
        if (kn < niter) {
            int sn = kn % STAGES;
            #pragma unroll
            for (int h = 0; h < 2; h++) {
                int k0 = kn * BKT + h * 16;
                cp16(As_base + (sn * 2 + h) * 4096 + a_sm, agp + k0);
                cp16(Bs_base + (sn * 2 + h) * 4096 + b_sm, bgp + (size_t)k0 * N);
            }
        }
        asm volatile("cp.async.commit_group;");

        #pragma unroll
        for (int h = 0; h < 2; h++) {
            unsigned a[2][4], b[8][2];
            unsigned a_base = As_base + (s * 2 + h) * 4096;
            unsigned b_base = Bs_base + (s * 2 + h) * 4096;
            #pragma unroll
            for (int mt = 0; mt < 2; mt++) {
                int lrow = wm * 32 + mt * 16 + a_lrow_off;
                unsigned addr = a_base + (unsigned)((lrow * 2 + (a_ch ^ ((lrow >> 2) & 1))) * 16);
                ldsm_x4(a[mt], addr);
            }
            #pragma unroll
            for (int p = 0; p < 4; p++) {
                int ch = ((wn * 64 + p * 16) >> 3) + b_choff;
                unsigned addr = b_base + (unsigned)((b_lk * 16 + (ch ^ (b_lk & 7))) * 16);
                ldsm_x4_t(b[2 * p][0], b[2 * p][1], b[2 * p + 1][0], b[2 * p + 1][1], addr);
            }
            #pragma unroll
            for (int mt = 0; mt < 2; mt++)
                #pragma unroll
                for (int nt = 0; nt < 8; nt++)
                    mma_f16(acc[mt][nt], a[mt], b[nt]);
        }

        asm volatile("cp.async.wait_group %0;" :: "n"(STAGES - 2) : "memory");
        __syncthreads();
    }

    // epilogue: thread (g,kq) owns rows (+g, +g+8), cols kq*2, kq*2+1 per 8-col tile
    #pragma unroll
    for (int mt = 0; mt < 2; mt++) {
        int r_lo = row0 + wm * 32 + mt * 16 + g;
        int r_hi = r_lo + 8;
        size_t dlo = 0, dhi = 0;
        if (EPI == 1) {
            dlo = (size_t)win_row_to_src(r_lo) * CC;
            dhi = (size_t)win_row_to_src(r_hi) * CC;
        }
        #pragma unroll
        for (int nt = 0; nt < 8; nt++) {
            int c = col0 + wn * 64 + nt * 8 + kq * 2;
            float bs0 = bias[c], bs1 = bias[c + 1];
            float v0 = acc[mt][nt][0] + bs0;
            float v1 = acc[mt][nt][1] + bs1;
            float v2 = acc[mt][nt][2] + bs0;
            float v3 = acc[mt][nt][3] + bs1;
            if (EPI == 0) {
                *(__half2*)&CoutH[(size_t)r_lo * N + c] = __floats2half2_rn(v0, v1);
                *(__half2*)&CoutH[(size_t)r_hi * N + c] = __floats2half2_rn(v2, v3);
            } else if (EPI == 1) {
                CoutF[dlo + c]     = resid[dlo + c]     + v0;
                CoutF[dlo + c + 1] = resid[dlo + c + 1] + v1;
                CoutF[dhi + c]     = resid[dhi + c]     + v2;
                CoutF[dhi + c + 1] = resid[dhi + c + 1] + v3;
            } else if (EPI == 2) {
                const float is2 = 0.7071067811865476f;
                float g0 = 0.5f * v0 * (1.0f + erff(v0 * is2));
                float g1v = 0.5f * v1 * (1.0f + erff(v1 * is2));
                float g2v = 0.5f * v2 * (1.0f + erff(v2 * is2));
                float g3 = 0.5f * v3 * (1.0f + erff(v3 * is2));
                *(__half2*)&CoutH[(size_t)r_lo * N + c] = __floats2half2_rn(g0, g1v);
                *(__half2*)&CoutH[(size_t)r_hi * N + c] = __floats2half2_rn(g2v, g3);
            } else {  // EPI == 3
                size_t o = (size_t)r_lo * N + c;
                CoutF[o]     += v0;
                CoutF[o + 1] += v1;
                size_t o2 = (size_t)r_hi * N + c;
                CoutF[o2]     += v2;
                CoutF[o2 + 1] += v3;
            }
        }
    }
}

// ---------------- windowed attention (fp16 in/out, fp32 math) ----------------
__global__ void __launch_bounds__(256) attn_kernel(
    const __half* __restrict__ qkv, const float* __restrict__ rpb,
    __half* __restrict__ out)
{
    int blk = blockIdx.x;
    int w = blk / NHEAD, head = blk - w * NHEAD;
    int wi = w & (NWIN - 1);
    int wh = wi >> 3, ww = wi & 7;

    __shared__ float q[NTOK * HD];
    __shared__ float k[NTOK * HD];
    __shared__ float v[NTOK * HD];
    __shared__ float at[NTOK * 52];

    int tid = threadIdx.x;
    size_t base = (size_t)w * NTOK * (3 * CC) + head * HD;
    const float scale = 0.17677669529663687f;
    for (int i = tid; i < NTOK * HD; i += 256) {
        int n = i >> 5, d = i & 31;
        size_t o = base + (size_t)n * (3 * CC) + d;
        q[i] = __half2float(qkv[o]) * scale;
        k[i] = __half2float(qkv[o + CC]);
        v[i] = __half2float(qkv[o + 2 * CC]);
    }
    __syncthreads();

    for (int e = tid; e < NTOK * NTOK; e += 256) {
        int n = e / NTOK, m = e - n * NTOK;
        float s = 0.0f;
        #pragma unroll
        for (int d = 0; d < HD; d++) s = fmaf(q[n * HD + d], k[m * HD + d], s);
        int r1 = n / WS, c1 = n - r1 * WS;
        int r2 = m / WS, c2 = m - r2 * WS;
        int idx = (r1 - r2 + WS - 1) * (2 * WS - 1) + (c1 - c2 + WS - 1);
        s += rpb[idx * NHEAD + head];
        int gh1 = wh * WS + r1, gw1 = ww * WS + c1;
        int gh2 = wh * WS + r2, gw2 = ww * WS + c2;
        int id1 = (gh1 < 49 ? 0 : (gh1 < 53 ? 1 : 2)) * 3 + (gw1 < 49 ? 0 : (gw1 < 53 ? 1 : 2));
        int id2 = (gh2 < 49 ? 0 : (gh2 < 53 ? 1 : 2)) * 3 + (gw2 < 49 ? 0 : (gw2 < 53 ? 1 : 2));
        if (id1 != id2) s -= 100.0f;
        at[n * 52 + m] = s;
    }
    __syncthreads();

    if (tid < NTOK) {
        float mx = -1e30f;
        for (int m2 = 0; m2 < NTOK; m2++) mx = fmaxf(mx, at[tid * 52 + m2]);
        float sum = 0.0f;
        for (int m2 = 0; m2 < NTOK; m2++) {
            float e2 = __expf(at[tid * 52 + m2] - mx);
            at[tid * 52 + m2] = e2;
            sum += e2;
        }
        float inv = 1.0f / sum;
        for (int m2 = 0; m2 < NTOK; m2++) at[tid * 52 + m2] *= inv;
    }
    __syncthreads();

    for (int i = tid; i < NTOK * HD; i += 256) {
        int n = i >> 5, d = i & 31;
        float s = 0.0f;
        #pragma unroll
        for (int m2 = 0; m2 < NTOK; m2++) s = fmaf(at[n * 52 + m2], v[m2 * HD + d], s);
        out[(size_t)(w * NTOK + n) * CC + head * HD + d] = __float2half(s);
    }
}

// ---------------- launch ----------------
extern "C" void kernel_launch(void* const* d_in, const int* in_sizes, int n_in,
                              void* d_out, int out_size)
{
    const float* x      = (const float*)d_in[0];
    const float* g1     = (const float*)d_in[1];
    const float* b1     = (const float*)d_in[2];
    const float* w_qkv  = (const float*)d_in[3];
    const float* b_qkv  = (const float*)d_in[4];
    const float* w_proj = (const float*)d_in[5];
    const float* b_proj = (const float*)d_in[6];
    const float* rpb    = (const float*)d_in[7];
    const float* g2     = (const float*)d_in[8];
    const float* b2     = (const float*)d_in[9];
    const float* w1     = (const float*)d_in[10];
    const float* bm1    = (const float*)d_in[11];
    const float* w2     = (const float*)d_in[12];
    const float* bm2    = (const float*)d_in[13];
    float* out = (float*)d_out;

    static __half *p_hwin = nullptr, *p_qkv = nullptr, *p_attn = nullptr,
                  *p_h2 = nullptr, *p_hid = nullptr,
                  *p_wqkv = nullptr, *p_wproj = nullptr, *p_w1 = nullptr, *p_w2 = nullptr;
    if (!p_hwin) {
        cudaGetSymbolAddress((void**)&p_hwin,  g_hwin);
        cudaGetSymbolAddress((void**)&p_qkv,   g_qkv);
        cudaGetSymbolAddress((void**)&p_attn,  g_attn);
        cudaGetSymbolAddress((void**)&p_h2,    g_h2);
        cudaGetSymbolAddress((void**)&p_hid,   g_hid);
        cudaGetSymbolAddress((void**)&p_wqkv,  g_wqkv);
        cudaGetSymbolAddress((void**)&p_wproj, g_wproj);
        cudaGetSymbolAddress((void**)&p_w1,    g_w1);
        cudaGetSymbolAddress((void**)&p_w2,    g_w2);
    }

    // 0. weight conversions (tiny)
    f2h_kernel<<<(CC * 3 * CC) / 4 / 256, 256>>>(w_qkv, p_wqkv, CC * 3 * CC);
    f2h_kernel<<<(CC * CC) / 4 / 256, 256>>>(w_proj, p_wproj, CC * CC);
    f2h_kernel<<<(CC * HID) / 4 / 256, 256>>>(w1, p_w1, CC * HID);
    f2h_kernel<<<(HID * CC) / 4 / 256, 256>>>(w2, p_w2, HID * CC);

    // 1. LN1 + roll + window partition -> half
    ln_kernel<true><<<MROWS, 128>>>(x, g1, b1, p_hwin);
    // 2. QKV GEMM  [100352,384] @ [384,1152] -> half
    hgemm_kernel<0><<<dim3(1152 / BN, MROWS / BM), 256>>>(p_hwin, p_wqkv, b_qkv, nullptr, p_qkv, nullptr, MROWS, 3 * CC, CC);
    // 3. windowed attention -> half
    attn_kernel<<<BNW * NHEAD, 256>>>(p_qkv, rpb, p_attn);
    // 4. proj GEMM + window reverse + unshift + shortcut residual -> fp32 d_out
    hgemm_kernel<1><<<dim3(CC / BN, MROWS / BM), 256>>>(p_attn, p_wproj, b_proj, out, nullptr, x, MROWS, CC, CC);
    // 5. LN2 -> half
    ln_kernel<false><<<MROWS, 128>>>(out, g2, b2, p_h2);
    // 6. MLP1 + GELU  [100352,384] @ [384,1536] -> half
    hgemm_kernel<2><<<dim3(HID / BN, MROWS / BM), 256>>>(p_h2, p_w1, bm1, nullptr, p_hid, nullptr, MROWS, HID, CC);
    // 7. MLP2 + residual into fp32 d_out  [100352,1536] @ [1536,384]
    hgemm_kernel<3><<<dim3(CC / BN, MROWS / BM), 256>>>(p_hid, p_w2, bm2, out, nullptr, nullptr, MROWS, CC, HID);
}